// round 6
// baseline (speedup 1.0000x reference)
#include <cuda_runtime.h>
#include <stdint.h>

// diag(A) @ B : out[i][j] = A[i] * B[i][j]
// N = 8192 rows, M = 8192 cols, fp32. Pure HBM-streaming kernel.
//
// R5: 256-bit global accesses (Blackwell LDG.E.256 / STG.256 via
// ld/st.global.cs.v8.f32). One block == one row: 512 threads x 2 x v8
// = 8192 floats. Loads front-batched, streaming hints both directions.

#define THREADS 512
#define VCHUNK  8            // floats per 256-bit access
#define UNROLL  2            // 512 * 2 * 8 = 8192 = M

__device__ __forceinline__ void ldg256_cs(const float* __restrict__ p, float v[8]) {
    asm volatile(
        "ld.global.cs.v8.f32 {%0,%1,%2,%3,%4,%5,%6,%7}, [%8];"
        : "=f"(v[0]), "=f"(v[1]), "=f"(v[2]), "=f"(v[3]),
          "=f"(v[4]), "=f"(v[5]), "=f"(v[6]), "=f"(v[7])
        : "l"(p));
}

__device__ __forceinline__ void stg256_cs(float* __restrict__ p, const float v[8]) {
    asm volatile(
        "st.global.cs.v8.f32 [%0], {%1,%2,%3,%4,%5,%6,%7,%8};"
        :: "l"(p),
           "f"(v[0]), "f"(v[1]), "f"(v[2]), "f"(v[3]),
           "f"(v[4]), "f"(v[5]), "f"(v[6]), "f"(v[7])
        : "memory");
}

__global__ void __launch_bounds__(THREADS) diag_scale_row_v8(
    const float* __restrict__ A,
    const float* __restrict__ B,
    float* __restrict__ out)
{
    const int row = blockIdx.x;                    // 8192 blocks = 8192 rows
    const float a = __ldg(&A[row]);

    // Row base in floats; thread covers two 256-bit chunks, stride 4096 floats.
    const long long base = (long long)row * 8192 + (long long)threadIdx.x * VCHUNK;

    float b[UNROLL][VCHUNK];
#pragma unroll
    for (int k = 0; k < UNROLL; k++) {
        ldg256_cs(B + base + (long long)k * (THREADS * VCHUNK), b[k]);
    }

#pragma unroll
    for (int k = 0; k < UNROLL; k++) {
        float o[VCHUNK];
#pragma unroll
        for (int j = 0; j < VCHUNK; j++) o[j] = a * b[k][j];
        stg256_cs(out + base + (long long)k * (THREADS * VCHUNK), o);
    }
}

extern "C" void kernel_launch(void* const* d_in, const int* in_sizes, int n_in,
                              void* d_out, int out_size)
{
    const float* A = (const float*)d_in[0];
    const float* B = (const float*)d_in[1];
    float* out = (float*)d_out;

    int n_rows = (int)((long long)out_size / 8192);  // 8192

    diag_scale_row_v8<<<n_rows, THREADS>>>(A, B, out);
}

// round 7
// speedup vs baseline: 1.0012x; 1.0012x over previous
#include <cuda_runtime.h>
#include <stdint.h>

// diag(A) @ B : out[i][j] = A[i] * B[i][j]
// N = 8192 rows, M = 8192 cols, fp32. Pure HBM-streaming kernel.
//
// R6: half-row per block. 256 threads x 4 float4 = 4096 floats = M/2.
// Grid 16384 -> finer CTA granularity for load balancing across L2 dies,
// full occupancy (8 CTAs/SM), MLP_p1=4 front-batched loads, streaming hints.

#define THREADS 256
#define UNROLL  4   // 256 * 4 * 4 floats = 4096 = M/2 (half row per block)

__global__ void __launch_bounds__(THREADS) diag_scale_halfrow(
    const float* __restrict__ A,
    const float4* __restrict__ B4,
    float4* __restrict__ out4)
{
    const int row = blockIdx.x >> 1;               // 2 blocks per row
    const float a = __ldg(&A[row]);

    // Each block covers 1024 float4 (16 KB); block base in float4 units.
    const long long base = (long long)blockIdx.x * (THREADS * UNROLL) + threadIdx.x;

    // Front-batch all loads: 4 independent LDG.128 in flight per thread.
    float4 b[UNROLL];
#pragma unroll
    for (int k = 0; k < UNROLL; k++) {
        b[k] = __ldcs(&B4[base + (long long)k * THREADS]);
    }

#pragma unroll
    for (int k = 0; k < UNROLL; k++) {
        float4 o;
        o.x = a * b[k].x;
        o.y = a * b[k].y;
        o.z = a * b[k].z;
        o.w = a * b[k].w;
        __stcs(&out4[base + (long long)k * THREADS], o);
    }
}

extern "C" void kernel_launch(void* const* d_in, const int* in_sizes, int n_in,
                              void* d_out, int out_size)
{
    const float* A = (const float*)d_in[0];
    const float4* B4 = (const float4*)d_in[1];
    float4* out4 = (float4*)d_out;

    // 2 blocks per row; rows = out_size / M, M = 8192.
    int n_rows = (int)((long long)out_size / 8192);
    int blocks = n_rows * 2;                       // 16384

    diag_scale_halfrow<<<blocks, THREADS>>>(A, B4, out4);
}